// round 1
// baseline (speedup 1.0000x reference)
#include <cuda_runtime.h>

#define N_NODES 50000
#define N_EDGES 800000
#define HID 32
#define NLAYERS 4
#define C_IN 64
#define C_OUT 64

// ---------------- device scratch (no runtime allocation allowed) ----------------
__device__ float g_h[N_NODES * HID];      // node features
__device__ float g_x[N_NODES * 2];        // 2D coords (z is provably always 0)
__device__ float g_A[N_NODES * HID];      // h @ W1[0:32]  + b1
__device__ float g_B[N_NODES * HID];      // h @ W1[32:64]
__device__ float g_agg[N_NODES * HID];    // edge-message sum per node
__device__ float g_xacc[N_NODES * 2];     // coord update accumulator
__device__ float g_cnt[N_NODES];          // edge count per row-node

__device__ __forceinline__ float silu(float v) {
    // v * sigmoid(v); RCP(inf)=0 handles large-negative v correctly
    float s = __fdividef(1.0f, 1.0f + __expf(-v));
    return v * s;
}

// out[32] = act(in[IN] @ Wsh + bias). Wsh is [IN][32] row-major in shared, 16B aligned.
template<int IN, bool DOSILU, bool HASBIAS>
__device__ __forceinline__ void matvec32(const float* __restrict__ in,
                                         const float* __restrict__ Wsh,
                                         const float* __restrict__ bsh,
                                         float* __restrict__ out)
{
    float4 acc[8];
#pragma unroll
    for (int j = 0; j < 8; j++) {
        if (HASBIAS) acc[j] = reinterpret_cast<const float4*>(bsh)[j];
        else         acc[j] = make_float4(0.f, 0.f, 0.f, 0.f);
    }
#pragma unroll
    for (int i = 0; i < IN; i++) {
        float v = in[i];
        const float4* w = reinterpret_cast<const float4*>(Wsh + i * 32);
#pragma unroll
        for (int j = 0; j < 8; j++) {
            float4 ww = w[j];
            acc[j].x = fmaf(v, ww.x, acc[j].x);
            acc[j].y = fmaf(v, ww.y, acc[j].y);
            acc[j].z = fmaf(v, ww.z, acc[j].z);
            acc[j].w = fmaf(v, ww.w, acc[j].w);
        }
    }
#pragma unroll
    for (int j = 0; j < 8; j++) {
        float4 a = acc[j];
        if (DOSILU) { a.x = silu(a.x); a.y = silu(a.y); a.z = silu(a.z); a.w = silu(a.w); }
        out[4 * j + 0] = a.x; out[4 * j + 1] = a.y; out[4 * j + 2] = a.z; out[4 * j + 3] = a.w;
    }
}

// ---------------- init: h = [t,data]@emb_in + b, x = pos, zero scratch ----------------
__global__ __launch_bounds__(256) void k_init(
    const float* __restrict__ data, const float* __restrict__ pos,
    const float* __restrict__ tptr,
    const float* __restrict__ w, const float* __restrict__ b)
{
    __shared__ __align__(16) float sW[65 * 32];
    __shared__ __align__(16) float sb[32];
    int t = threadIdx.x;
    for (int i = t; i < 65 * 32; i += blockDim.x) sW[i] = w[i];
    if (t < 32) sb[t] = b[t];
    __syncthreads();

    int n = blockIdx.x * blockDim.x + t;
    if (n >= N_NODES) return;

    float in[65];
    in[0] = tptr[0];
    const float4* dv = reinterpret_cast<const float4*>(data + n * 64);
#pragma unroll
    for (int i = 0; i < 16; i++) {
        float4 d = dv[i];
        in[1 + 4 * i + 0] = d.x; in[1 + 4 * i + 1] = d.y;
        in[1 + 4 * i + 2] = d.z; in[1 + 4 * i + 3] = d.w;
    }
    float hv[32];
    matvec32<65, false, true>(in, sW, sb, hv);

    float4* hout = reinterpret_cast<float4*>(g_h + n * 32);
    float4* aout = reinterpret_cast<float4*>(g_agg + n * 32);
#pragma unroll
    for (int j = 0; j < 8; j++) {
        hout[j] = make_float4(hv[4 * j], hv[4 * j + 1], hv[4 * j + 2], hv[4 * j + 3]);
        aout[j] = make_float4(0.f, 0.f, 0.f, 0.f);
    }
    reinterpret_cast<float2*>(g_x)[n] = reinterpret_cast<const float2*>(pos)[n];
    reinterpret_cast<float2*>(g_xacc)[n] = make_float2(0.f, 0.f);
    g_cnt[n] = 0.f;
}

__global__ __launch_bounds__(256) void k_cnt(const int* __restrict__ row)
{
    int e = blockIdx.x * blockDim.x + threadIdx.x;
    if (e >= N_EDGES) return;
    atomicAdd(&g_cnt[row[e]], 1.0f);
}

// ---------------- per layer: A = h@W1a + b1, B = h@W1b ----------------
__global__ __launch_bounds__(256) void k_AB(
    const float* __restrict__ ew1, const float* __restrict__ eb1)
{
    __shared__ __align__(16) float sW[64 * 32];
    __shared__ __align__(16) float sb[32];
    int t = threadIdx.x;
    for (int i = t; i < 64 * 32; i += blockDim.x) sW[i] = ew1[i];
    if (t < 32) sb[t] = eb1[t];
    __syncthreads();

    int n = blockIdx.x * blockDim.x + t;
    if (n >= N_NODES) return;

    float hv[32];
    const float4* hin = reinterpret_cast<const float4*>(g_h + n * 32);
#pragma unroll
    for (int i = 0; i < 8; i++) {
        float4 v = hin[i];
        hv[4 * i] = v.x; hv[4 * i + 1] = v.y; hv[4 * i + 2] = v.z; hv[4 * i + 3] = v.w;
    }
    float a[32], bb[32];
    matvec32<32, false, true >(hv, sW,            sb, a);
    matvec32<32, false, false>(hv, sW + 32 * 32,  sb, bb);

    float4* ao = reinterpret_cast<float4*>(g_A + n * 32);
    float4* bo = reinterpret_cast<float4*>(g_B + n * 32);
#pragma unroll
    for (int j = 0; j < 8; j++) {
        ao[j] = make_float4(a[4 * j], a[4 * j + 1], a[4 * j + 2], a[4 * j + 3]);
        bo[j] = make_float4(bb[4 * j], bb[4 * j + 1], bb[4 * j + 2], bb[4 * j + 3]);
    }
}

// ---------------- per layer: fused edge MLP + coord MLP + scatter ----------------
__global__ __launch_bounds__(256) void k_edge(
    const int* __restrict__ row, const int* __restrict__ col,
    const float* __restrict__ ea,
    const float* __restrict__ ew1,                       // layer slice of edge_w1 (66x32)
    const float* __restrict__ ew2, const float* __restrict__ eb2,
    const float* __restrict__ cw1, const float* __restrict__ cb1,
    const float* __restrict__ cw2)
{
    __shared__ __align__(16) float sW2[32 * 32];
    __shared__ __align__(16) float sC1[32 * 32];
    __shared__ __align__(16) float sb2[32], scb1[32], scw2[32], swr[32], swe[32];
    int t = threadIdx.x;
    for (int i = t; i < 1024; i += blockDim.x) { sW2[i] = ew2[i]; sC1[i] = cw1[i]; }
    if (t < 32) {
        sb2[t] = eb2[t]; scb1[t] = cb1[t]; scw2[t] = cw2[t];
        swr[t] = ew1[64 * 32 + t]; swe[t] = ew1[65 * 32 + t];
    }
    __syncthreads();

    int e = blockIdx.x * blockDim.x + t;
    if (e >= N_EDGES) return;

    int r = row[e], c = col[e];
    float2 xr = reinterpret_cast<const float2*>(g_x)[r];
    float2 xc = reinterpret_cast<const float2*>(g_x)[c];
    float dx = xr.x - xc.x, dy = xr.y - xc.y;
    float radial = dx * dx + dy * dy;
    float eav = ea[e];

    // first edge-MLP layer from precomputed A/B
    float t1[32];
    const float4* Ar = reinterpret_cast<const float4*>(g_A + r * 32);
    const float4* Bc = reinterpret_cast<const float4*>(g_B + c * 32);
#pragma unroll
    for (int j = 0; j < 8; j++) {
        float4 a = Ar[j], b = Bc[j];
        float4 wr4 = reinterpret_cast<const float4*>(swr)[j];
        float4 we4 = reinterpret_cast<const float4*>(swe)[j];
        t1[4 * j + 0] = silu(a.x + b.x + radial * wr4.x + eav * we4.x);
        t1[4 * j + 1] = silu(a.y + b.y + radial * wr4.y + eav * we4.y);
        t1[4 * j + 2] = silu(a.z + b.z + radial * wr4.z + eav * we4.z);
        t1[4 * j + 3] = silu(a.w + b.w + radial * wr4.w + eav * we4.w);
    }

    float m[32];
    matvec32<32, true, true>(t1, sW2, sb2, m);       // m = silu(t1@W2 + b2)

    float p[32];
    matvec32<32, true, true>(m, sC1, scb1, p);       // p = silu(m@Cw1 + cb1)
    float phi = 0.f;
#pragma unroll
    for (int j = 0; j < 32; j++) phi = fmaf(p[j], scw2[j], phi);

    atomicAdd(&g_xacc[2 * r + 0], dx * phi);
    atomicAdd(&g_xacc[2 * r + 1], dy * phi);
    float* aggr = g_agg + r * 32;
#pragma unroll
    for (int j = 0; j < 32; j++) atomicAdd(&aggr[j], m[j]);
}

// ---------------- per layer: coord update + node MLP (residual) ----------------
__global__ __launch_bounds__(256) void k_node(
    const float* __restrict__ nw1, const float* __restrict__ nb1,
    const float* __restrict__ nw2, const float* __restrict__ nb2)
{
    __shared__ __align__(16) float sW1[64 * 32];
    __shared__ __align__(16) float sW2[32 * 32];
    __shared__ __align__(16) float sb1[32], sb2[32];
    int t = threadIdx.x;
    for (int i = t; i < 64 * 32; i += blockDim.x) sW1[i] = nw1[i];
    for (int i = t; i < 32 * 32; i += blockDim.x) sW2[i] = nw2[i];
    if (t < 32) { sb1[t] = nb1[t]; sb2[t] = nb2[t]; }
    __syncthreads();

    int n = blockIdx.x * blockDim.x + t;
    if (n >= N_NODES) return;

    // coordinate update: x += xacc / max(cnt,1), then reset accumulator
    float cnt = fmaxf(g_cnt[n], 1.0f);
    float inv = __fdividef(1.0f, cnt);
    float2 xa = reinterpret_cast<float2*>(g_xacc)[n];
    float2 xv = reinterpret_cast<float2*>(g_x)[n];
    xv.x = fmaf(xa.x, inv, xv.x);
    xv.y = fmaf(xa.y, inv, xv.y);
    reinterpret_cast<float2*>(g_x)[n] = xv;
    reinterpret_cast<float2*>(g_xacc)[n] = make_float2(0.f, 0.f);

    float cat[64];
    float4* hio = reinterpret_cast<float4*>(g_h + n * 32);
    float4* agp = reinterpret_cast<float4*>(g_agg + n * 32);
#pragma unroll
    for (int i = 0; i < 8; i++) {
        float4 h4 = hio[i], a4 = agp[i];
        cat[4 * i + 0] = h4.x; cat[4 * i + 1] = h4.y; cat[4 * i + 2] = h4.z; cat[4 * i + 3] = h4.w;
        cat[32 + 4 * i + 0] = a4.x; cat[32 + 4 * i + 1] = a4.y;
        cat[32 + 4 * i + 2] = a4.z; cat[32 + 4 * i + 3] = a4.w;
        agp[i] = make_float4(0.f, 0.f, 0.f, 0.f);   // reset for next layer
    }
    float u[32];
    matvec32<64, true, true>(cat, sW1, sb1, u);
    float upd[32];
    matvec32<32, false, true>(u, sW2, sb2, upd);
#pragma unroll
    for (int i = 0; i < 8; i++) {
        hio[i] = make_float4(cat[4 * i + 0] + upd[4 * i + 0],
                             cat[4 * i + 1] + upd[4 * i + 1],
                             cat[4 * i + 2] + upd[4 * i + 2],
                             cat[4 * i + 3] + upd[4 * i + 3]);
    }
}

// ---------------- output projection ----------------
__global__ __launch_bounds__(256) void k_out(
    const float* __restrict__ w, const float* __restrict__ b,
    float* __restrict__ out)
{
    __shared__ __align__(16) float sW[32 * 64];
    __shared__ __align__(16) float sb[64];
    int t = threadIdx.x;
    for (int i = t; i < 32 * 64; i += blockDim.x) sW[i] = w[i];
    if (t < 64) sb[t] = b[t];
    __syncthreads();

    int n = blockIdx.x * blockDim.x + t;
    if (n >= N_NODES) return;

    float hv[32];
    const float4* hin = reinterpret_cast<const float4*>(g_h + n * 32);
#pragma unroll
    for (int i = 0; i < 8; i++) {
        float4 v = hin[i];
        hv[4 * i] = v.x; hv[4 * i + 1] = v.y; hv[4 * i + 2] = v.z; hv[4 * i + 3] = v.w;
    }
    float4 acc[16];
#pragma unroll
    for (int j = 0; j < 16; j++) acc[j] = reinterpret_cast<const float4*>(sb)[j];
#pragma unroll
    for (int i = 0; i < 32; i++) {
        float v = hv[i];
        const float4* wr = reinterpret_cast<const float4*>(sW + i * 64);
#pragma unroll
        for (int j = 0; j < 16; j++) {
            float4 ww = wr[j];
            acc[j].x = fmaf(v, ww.x, acc[j].x);
            acc[j].y = fmaf(v, ww.y, acc[j].y);
            acc[j].z = fmaf(v, ww.z, acc[j].z);
            acc[j].w = fmaf(v, ww.w, acc[j].w);
        }
    }
    float4* op = reinterpret_cast<float4*>(out + n * 64);
#pragma unroll
    for (int j = 0; j < 16; j++) op[j] = acc[j];
}

// ---------------- host launcher ----------------
extern "C" void kernel_launch(void* const* d_in, const int* in_sizes, int n_in,
                              void* d_out, int out_size)
{
    const float* data      = (const float*)d_in[0];
    const float* pos       = (const float*)d_in[1];
    const float* ea        = (const float*)d_in[2];
    const float* tptr      = (const float*)d_in[3];
    const int*   row       = (const int*)d_in[4];
    const int*   col       = (const int*)d_in[5];
    const float* emb_in_w  = (const float*)d_in[6];
    const float* emb_in_b  = (const float*)d_in[7];
    const float* emb_out_w = (const float*)d_in[8];
    const float* emb_out_b = (const float*)d_in[9];
    const float* edge_w1   = (const float*)d_in[10];
    const float* edge_b1   = (const float*)d_in[11];
    const float* edge_w2   = (const float*)d_in[12];
    const float* edge_b2   = (const float*)d_in[13];
    const float* node_w1   = (const float*)d_in[14];
    const float* node_b1   = (const float*)d_in[15];
    const float* node_w2   = (const float*)d_in[16];
    const float* node_b2   = (const float*)d_in[17];
    const float* coord_w1  = (const float*)d_in[18];
    const float* coord_b1  = (const float*)d_in[19];
    const float* coord_w2  = (const float*)d_in[20];

    const int NB_N = (N_NODES + 255) / 256;
    const int NB_E = (N_EDGES + 255) / 256;

    k_init<<<NB_N, 256>>>(data, pos, tptr, emb_in_w, emb_in_b);
    k_cnt<<<NB_E, 256>>>(row);

    for (int l = 0; l < NLAYERS; l++) {
        const float* ew1 = edge_w1 + l * 66 * 32;
        k_AB<<<NB_N, 256>>>(ew1, edge_b1 + l * 32);
        k_edge<<<NB_E, 256>>>(row, col, ea, ew1,
                              edge_w2 + l * 1024, edge_b2 + l * 32,
                              coord_w1 + l * 1024, coord_b1 + l * 32,
                              coord_w2 + l * 32);
        k_node<<<NB_N, 256>>>(node_w1 + l * 2048, node_b1 + l * 32,
                              node_w2 + l * 1024, node_b2 + l * 32);
    }
    k_out<<<NB_N, 256>>>(emb_out_w, emb_out_b, (float*)d_out);
}

// round 3
// speedup vs baseline: 1.4015x; 1.4015x over previous
#include <cuda_runtime.h>

#define N_NODES 50000
#define N_EDGES 800000
#define HID 32
#define NLAYERS 4

// ---------------- device scratch (no runtime allocation allowed) ----------------
__device__ float g_h[N_NODES * HID];      // node features
__device__ float g_x[N_NODES * 2];        // 2D coords (z provably stays 0)
__device__ float g_A[N_NODES * HID];      // h @ W1[0:32] + b1
__device__ float g_B[N_NODES * HID];      // h @ W1[32:64]
__device__ float g_agg[N_NODES * HID];    // edge-message sum per node
__device__ float g_xacc[N_NODES * 2];     // coord update accumulator
__device__ int   g_hist[N_NODES];         // per-row edge count
__device__ int   g_cur[N_NODES];          // scatter cursor (exclusive offsets)
__device__ int   g_rs[N_EDGES];           // sorted rows
__device__ int   g_cs[N_EDGES];           // cols permuted
__device__ float g_eas[N_EDGES];          // edge_attr permuted

__device__ __forceinline__ float silu(float x) {
    // x*sigmoid(x) = 0.5x*(1+tanh(0.5x)); tanh.approx err ~1e-4, fine at 1e-3 tol
    float h = 0.5f * x, t;
    asm("tanh.approx.f32 %0, %1;" : "=f"(t) : "f"(h));
    return fmaf(h, t, h);
}

__device__ __forceinline__ float2 ffma2(float2 a, float2 b, float2 c) {
    float2 d;
    asm("fma.rn.f32x2 %0, %1, %2, %3;"
        : "=l"(reinterpret_cast<unsigned long long&>(d))
        : "l"(reinterpret_cast<unsigned long long&>(a)),
          "l"(reinterpret_cast<unsigned long long&>(b)),
          "l"(reinterpret_cast<unsigned long long&>(c)));
    return d;
}

// out[32] = act(in[IN] @ Wsh + bias). Wsh [IN][32] row-major in shared, 16B aligned.
template<int IN, bool DOSILU, bool HASBIAS>
__device__ __forceinline__ void matvec32(const float* __restrict__ in,
                                         const float* __restrict__ Wsh,
                                         const float* __restrict__ bsh,
                                         float* __restrict__ out)
{
    float2 acc[16];
#pragma unroll
    for (int j = 0; j < 16; j++)
        acc[j] = HASBIAS ? reinterpret_cast<const float2*>(bsh)[j] : make_float2(0.f, 0.f);
#pragma unroll
    for (int i = 0; i < IN; i++) {
        float v = in[i];
        float2 vv = make_float2(v, v);
        const float4* w = reinterpret_cast<const float4*>(Wsh + i * 32);
#pragma unroll
        for (int j = 0; j < 8; j++) {
            float4 w4 = w[j];
            acc[2 * j]     = ffma2(vv, make_float2(w4.x, w4.y), acc[2 * j]);
            acc[2 * j + 1] = ffma2(vv, make_float2(w4.z, w4.w), acc[2 * j + 1]);
        }
    }
#pragma unroll
    for (int j = 0; j < 16; j++) {
        float a = acc[j].x, b = acc[j].y;
        if (DOSILU) { a = silu(a); b = silu(b); }
        out[2 * j] = a; out[2 * j + 1] = b;
    }
}

// ---------------- init: h = [t,data]@emb_in + b, x = pos, zero scratch ----------------
__global__ __launch_bounds__(256) void k_init(
    const float* __restrict__ data, const float* __restrict__ pos,
    const float* __restrict__ tptr,
    const float* __restrict__ w, const float* __restrict__ b)
{
    __shared__ __align__(16) float sW[65 * 32];
    __shared__ __align__(16) float sb[32];
    int t = threadIdx.x;
    for (int i = t; i < 65 * 32; i += blockDim.x) sW[i] = w[i];
    if (t < 32) sb[t] = b[t];
    __syncthreads();

    int n = blockIdx.x * blockDim.x + t;
    if (n >= N_NODES) return;

    float in[65];
    in[0] = tptr[0];
    const float4* dv = reinterpret_cast<const float4*>(data + n * 64);
#pragma unroll
    for (int i = 0; i < 16; i++) {
        float4 d = dv[i];
        in[1 + 4 * i + 0] = d.x; in[1 + 4 * i + 1] = d.y;
        in[1 + 4 * i + 2] = d.z; in[1 + 4 * i + 3] = d.w;
    }
    float hv[32];
    matvec32<65, false, true>(in, sW, sb, hv);

    float4* hout = reinterpret_cast<float4*>(g_h + n * 32);
    float4* aout = reinterpret_cast<float4*>(g_agg + n * 32);
#pragma unroll
    for (int j = 0; j < 8; j++) {
        hout[j] = make_float4(hv[4 * j], hv[4 * j + 1], hv[4 * j + 2], hv[4 * j + 3]);
        aout[j] = make_float4(0.f, 0.f, 0.f, 0.f);
    }
    reinterpret_cast<float2*>(g_x)[n] = reinterpret_cast<const float2*>(pos)[n];
    reinterpret_cast<float2*>(g_xacc)[n] = make_float2(0.f, 0.f);
    g_hist[n] = 0;
}

// ---------------- counting sort of edges by row ----------------
__global__ __launch_bounds__(256) void k_hist(const int* __restrict__ row)
{
    int e = blockIdx.x * blockDim.x + threadIdx.x;
    if (e < N_EDGES) atomicAdd(&g_hist[row[e]], 1);
}

__global__ __launch_bounds__(1024) void k_scan()
{
    __shared__ int buf[1024];
    __shared__ int carry;
    int t = threadIdx.x;
    if (t == 0) carry = 0;
    __syncthreads();
    for (int base = 0; base < N_NODES; base += 1024) {
        int i = base + t;
        int v = (i < N_NODES) ? g_hist[i] : 0;
        buf[t] = v;
        __syncthreads();
#pragma unroll
        for (int d = 1; d < 1024; d <<= 1) {
            int x = (t >= d) ? buf[t - d] : 0;
            __syncthreads();
            buf[t] += x;
            __syncthreads();
        }
        int c = carry;
        if (i < N_NODES) g_cur[i] = c + buf[t] - v;   // exclusive prefix
        __syncthreads();
        if (t == 1023) carry = c + buf[1023];
        __syncthreads();
    }
}

__global__ __launch_bounds__(256) void k_scatter(
    const int* __restrict__ row, const int* __restrict__ col,
    const float* __restrict__ ea)
{
    int e = blockIdx.x * blockDim.x + threadIdx.x;
    if (e >= N_EDGES) return;
    int r = row[e];
    int p = atomicAdd(&g_cur[r], 1);
    g_rs[p] = r;
    g_cs[p] = col[e];
    g_eas[p] = ea[e];
}

// ---------------- per layer: A = h@W1a + b1, B = h@W1b ----------------
__global__ __launch_bounds__(256) void k_AB(
    const float* __restrict__ ew1, const float* __restrict__ eb1)
{
    __shared__ __align__(16) float sW[64 * 32];
    __shared__ __align__(16) float sb[32];
    int t = threadIdx.x;
    for (int i = t; i < 64 * 32; i += blockDim.x) sW[i] = ew1[i];
    if (t < 32) sb[t] = eb1[t];
    __syncthreads();

    int n = blockIdx.x * blockDim.x + t;
    if (n >= N_NODES) return;

    float hv[32];
    const float4* hin = reinterpret_cast<const float4*>(g_h + n * 32);
#pragma unroll
    for (int i = 0; i < 8; i++) {
        float4 v = hin[i];
        hv[4 * i] = v.x; hv[4 * i + 1] = v.y; hv[4 * i + 2] = v.z; hv[4 * i + 3] = v.w;
    }
    float a[32], bb[32];
    matvec32<32, false, true >(hv, sW,           sb, a);
    matvec32<32, false, false>(hv, sW + 32 * 32, sb, bb);

    float4* ao = reinterpret_cast<float4*>(g_A + n * 32);
    float4* bo = reinterpret_cast<float4*>(g_B + n * 32);
#pragma unroll
    for (int j = 0; j < 8; j++) {
        ao[j] = make_float4(a[4 * j], a[4 * j + 1], a[4 * j + 2], a[4 * j + 3]);
        bo[j] = make_float4(bb[4 * j], bb[4 * j + 1], bb[4 * j + 2], bb[4 * j + 3]);
    }
}

// ---------------- per layer: fused edge MLP + coord MLP, warp-per-32-edges ----------------
#define WPB 4   // warps per block
__global__ __launch_bounds__(32 * WPB) void k_edge(
    const float* __restrict__ ew1,                       // layer slice of edge_w1 (66x32)
    const float* __restrict__ ew2, const float* __restrict__ eb2,
    const float* __restrict__ cw1, const float* __restrict__ cb1,
    const float* __restrict__ cw2)
{
    __shared__ __align__(16) float sW2[32 * 32];
    __shared__ __align__(16) float sC1[32 * 32];
    __shared__ __align__(16) float sb2[32], scb1[32], scw2[32], swr[32], swe[32];
    __shared__ __align__(16) float sT[WPB][33 * 32];     // per-warp 32x32 tile (padded)

    int t = threadIdx.x;
    for (int i = t; i < 1024; i += blockDim.x) { sW2[i] = ew2[i]; sC1[i] = cw1[i]; }
    if (t < 32) {
        sb2[t] = eb2[t]; scb1[t] = cb1[t]; scw2[t] = cw2[t];
        swr[t] = ew1[64 * 32 + t]; swe[t] = ew1[65 * 32 + t];
    }
    __syncthreads();

    int warp = t >> 5, l = t & 31;
    int e = (blockIdx.x * WPB + warp) * 32 + l;
    if (e >= N_EDGES) return;                            // N_EDGES % 32 == 0: warp-uniform
    float* T = sT[warp];

    int r = g_rs[e], c = g_cs[e];
    float eav = g_eas[e];
    float2 xr = reinterpret_cast<const float2*>(g_x)[r];
    float2 xc = reinterpret_cast<const float2*>(g_x)[c];
    float dx = xr.x - xc.x, dy = xr.y - xc.y;
    float radial = dx * dx + dy * dy;
    float wrl = swr[l], wel = swe[l];

    // cooperative t1 tile: iteration k = edge k of tile, lane l = feature l
#pragma unroll
    for (int k = 0; k < 32; k++) {
        int   rk   = __shfl_sync(0xFFFFFFFFu, r, k);
        int   ck   = __shfl_sync(0xFFFFFFFFu, c, k);
        float radk = __shfl_sync(0xFFFFFFFFu, radial, k);
        float eak  = __shfl_sync(0xFFFFFFFFu, eav, k);
        float val = __ldg(&g_A[rk * 32 + l]) + __ldg(&g_B[ck * 32 + l])
                  + radk * wrl + eak * wel;
        T[l * 33 + k] = silu(val);                       // sT[feature][edge]
    }
    __syncwarp();

    // m = silu(t1 @ W2 + b2): lane l = edge l reads its t1 column
    float2 acc[16];
#pragma unroll
    for (int j = 0; j < 16; j++) acc[j] = reinterpret_cast<const float2*>(sb2)[j];
#pragma unroll
    for (int i = 0; i < 32; i++) {
        float v = T[i * 33 + l];
        float2 vv = make_float2(v, v);
        const float4* w = reinterpret_cast<const float4*>(sW2 + i * 32);
#pragma unroll
        for (int j = 0; j < 8; j++) {
            float4 w4 = w[j];
            acc[2 * j]     = ffma2(vv, make_float2(w4.x, w4.y), acc[2 * j]);
            acc[2 * j + 1] = ffma2(vv, make_float2(w4.z, w4.w), acc[2 * j + 1]);
        }
    }
    float m[32];
#pragma unroll
    for (int j = 0; j < 16; j++) { m[2 * j] = silu(acc[j].x); m[2 * j + 1] = silu(acc[j].y); }

    // coord MLP: phi = silu(m @ C1 + cb1) . cw2
#pragma unroll
    for (int j = 0; j < 16; j++) acc[j] = reinterpret_cast<const float2*>(scb1)[j];
#pragma unroll
    for (int i = 0; i < 32; i++) {
        float2 vv = make_float2(m[i], m[i]);
        const float4* w = reinterpret_cast<const float4*>(sC1 + i * 32);
#pragma unroll
        for (int j = 0; j < 8; j++) {
            float4 w4 = w[j];
            acc[2 * j]     = ffma2(vv, make_float2(w4.x, w4.y), acc[2 * j]);
            acc[2 * j + 1] = ffma2(vv, make_float2(w4.z, w4.w), acc[2 * j + 1]);
        }
    }
    float phi = 0.f;
#pragma unroll
    for (int j = 0; j < 16; j++) {
        phi = fmaf(silu(acc[j].x), scw2[2 * j],     phi);
        phi = fmaf(silu(acc[j].y), scw2[2 * j + 1], phi);
    }

    // store m tile: lane l writes its column (only lane l ever touched column l)
#pragma unroll
    for (int j = 0; j < 32; j++) T[j * 33 + l] = m[j];

    // coord segmented warp-reduction (rows sorted ascending within warp)
    {
        float vx = dx * phi, vy = dy * phi;
        int rprev = __shfl_up_sync(0xFFFFFFFFu, r, 1);
        bool head = (l == 0) || (r != rprev);
        unsigned mb = __ballot_sync(0xFFFFFFFFu, head);
        unsigned lem = 0xFFFFFFFFu >> (31 - l);
        int start = 31 - __clz(mb & lem);
#pragma unroll
        for (int d = 1; d < 32; d <<= 1) {
            float tx = __shfl_up_sync(0xFFFFFFFFu, vx, d);
            float ty = __shfl_up_sync(0xFFFFFFFFu, vy, d);
            if (l - d >= start) { vx += tx; vy += ty; }
        }
        bool tail = (l == 31) || ((mb >> (l + 1)) & 1u);
        if (tail) {
            atomicAdd(&g_xacc[2 * r + 0], vx);
            atomicAdd(&g_xacc[2 * r + 1], vy);
        }
    }
    __syncwarp();

    // message aggregation: lane j = feature j sweeps sorted edges; atomic per segment
    {
        int rn = __shfl_down_sync(0xFFFFFFFFu, r, 1);    // row of next edge
        float a = 0.f;
#pragma unroll
        for (int k = 0; k < 32; k++) {
            a += T[l * 33 + k];
            int rowe = __shfl_sync(0xFFFFFFFFu, r, k);
            int rne  = (k < 31) ? __shfl_sync(0xFFFFFFFFu, rn, k) : -1;
            if (rowe != rne) {
                atomicAdd(&g_agg[rowe * 32 + l], a);
                a = 0.f;
            }
        }
    }
}

// ---------------- per layer: coord update + node MLP (residual) ----------------
__global__ __launch_bounds__(256) void k_node(
    const float* __restrict__ nw1, const float* __restrict__ nb1,
    const float* __restrict__ nw2, const float* __restrict__ nb2)
{
    __shared__ __align__(16) float sW1[64 * 32];
    __shared__ __align__(16) float sW2[32 * 32];
    __shared__ __align__(16) float sb1[32], sb2[32];
    int t = threadIdx.x;
    for (int i = t; i < 64 * 32; i += blockDim.x) sW1[i] = nw1[i];
    for (int i = t; i < 32 * 32; i += blockDim.x) sW2[i] = nw2[i];
    if (t < 32) { sb1[t] = nb1[t]; sb2[t] = nb2[t]; }
    __syncthreads();

    int n = blockIdx.x * blockDim.x + t;
    if (n >= N_NODES) return;

    float cnt = (float)max(g_hist[n], 1);
    float inv = __fdividef(1.0f, cnt);
    float2 xa = reinterpret_cast<float2*>(g_xacc)[n];
    float2 xv = reinterpret_cast<float2*>(g_x)[n];
    xv.x = fmaf(xa.x, inv, xv.x);
    xv.y = fmaf(xa.y, inv, xv.y);
    reinterpret_cast<float2*>(g_x)[n] = xv;
    reinterpret_cast<float2*>(g_xacc)[n] = make_float2(0.f, 0.f);

    float cat[64];
    float4* hio = reinterpret_cast<float4*>(g_h + n * 32);
    float4* agp = reinterpret_cast<float4*>(g_agg + n * 32);
#pragma unroll
    for (int i = 0; i < 8; i++) {
        float4 h4 = hio[i], a4 = agp[i];
        cat[4 * i + 0] = h4.x; cat[4 * i + 1] = h4.y; cat[4 * i + 2] = h4.z; cat[4 * i + 3] = h4.w;
        cat[32 + 4 * i + 0] = a4.x; cat[32 + 4 * i + 1] = a4.y;
        cat[32 + 4 * i + 2] = a4.z; cat[32 + 4 * i + 3] = a4.w;
        agp[i] = make_float4(0.f, 0.f, 0.f, 0.f);       // reset for next layer
    }
    float u[32];
    matvec32<64, true, true>(cat, sW1, sb1, u);
    float upd[32];
    matvec32<32, false, true>(u, sW2, sb2, upd);
#pragma unroll
    for (int i = 0; i < 8; i++) {
        hio[i] = make_float4(cat[4 * i + 0] + upd[4 * i + 0],
                             cat[4 * i + 1] + upd[4 * i + 1],
                             cat[4 * i + 2] + upd[4 * i + 2],
                             cat[4 * i + 3] + upd[4 * i + 3]);
    }
}

// ---------------- output projection ----------------
__global__ __launch_bounds__(256) void k_out(
    const float* __restrict__ w, const float* __restrict__ b,
    float* __restrict__ out)
{
    __shared__ __align__(16) float sW[32 * 64];
    __shared__ __align__(16) float sb[64];
    int t = threadIdx.x;
    for (int i = t; i < 32 * 64; i += blockDim.x) sW[i] = w[i];
    if (t < 64) sb[t] = b[t];
    __syncthreads();

    int n = blockIdx.x * blockDim.x + t;
    if (n >= N_NODES) return;

    float hv[32];
    const float4* hin = reinterpret_cast<const float4*>(g_h + n * 32);
#pragma unroll
    for (int i = 0; i < 8; i++) {
        float4 v = hin[i];
        hv[4 * i] = v.x; hv[4 * i + 1] = v.y; hv[4 * i + 2] = v.z; hv[4 * i + 3] = v.w;
    }
    float2 acc[32];
#pragma unroll
    for (int j = 0; j < 32; j++) acc[j] = reinterpret_cast<const float2*>(sb)[j];
#pragma unroll
    for (int i = 0; i < 32; i++) {
        float2 vv = make_float2(hv[i], hv[i]);
        const float4* wr = reinterpret_cast<const float4*>(sW + i * 64);
#pragma unroll
        for (int j = 0; j < 16; j++) {
            float4 w4 = wr[j];
            acc[2 * j]     = ffma2(vv, make_float2(w4.x, w4.y), acc[2 * j]);
            acc[2 * j + 1] = ffma2(vv, make_float2(w4.z, w4.w), acc[2 * j + 1]);
        }
    }
    float2* op = reinterpret_cast<float2*>(out + n * 64);
#pragma unroll
    for (int j = 0; j < 32; j++) op[j] = acc[j];
}

// ---------------- host launcher ----------------
extern "C" void kernel_launch(void* const* d_in, const int* in_sizes, int n_in,
                              void* d_out, int out_size)
{
    const float* data      = (const float*)d_in[0];
    const float* pos       = (const float*)d_in[1];
    const float* ea        = (const float*)d_in[2];
    const float* tptr      = (const float*)d_in[3];
    const int*   row       = (const int*)d_in[4];
    const int*   col       = (const int*)d_in[5];
    const float* emb_in_w  = (const float*)d_in[6];
    const float* emb_in_b  = (const float*)d_in[7];
    const float* emb_out_w = (const float*)d_in[8];
    const float* emb_out_b = (const float*)d_in[9];
    const float* edge_w1   = (const float*)d_in[10];
    const float* edge_b1   = (const float*)d_in[11];
    const float* edge_w2   = (const float*)d_in[12];
    const float* edge_b2   = (const float*)d_in[13];
    const float* node_w1   = (const float*)d_in[14];
    const float* node_b1   = (const float*)d_in[15];
    const float* node_w2   = (const float*)d_in[16];
    const float* node_b2   = (const float*)d_in[17];
    const float* coord_w1  = (const float*)d_in[18];
    const float* coord_b1  = (const float*)d_in[19];
    const float* coord_w2  = (const float*)d_in[20];

    const int NB_N = (N_NODES + 255) / 256;
    const int NB_E = (N_EDGES + 255) / 256;
    const int NB_T = (N_EDGES / 32 + WPB - 1) / WPB;     // edge tiles

    k_init<<<NB_N, 256>>>(data, pos, tptr, emb_in_w, emb_in_b);
    k_hist<<<NB_E, 256>>>(row);
    k_scan<<<1, 1024>>>();
    k_scatter<<<NB_E, 256>>>(row, col, ea);

    for (int l = 0; l < NLAYERS; l++) {
        const float* ew1 = edge_w1 + l * 66 * 32;
        k_AB<<<NB_N, 256>>>(ew1, edge_b1 + l * 32);
        k_edge<<<NB_T, 32 * WPB>>>(ew1,
                              edge_w2 + l * 1024, edge_b2 + l * 32,
                              coord_w1 + l * 1024, coord_b1 + l * 32,
                              coord_w2 + l * 32);
        k_node<<<NB_N, 256>>>(node_w1 + l * 2048, node_b1 + l * 32,
                              node_w2 + l * 1024, node_b2 + l * 32);
    }
    k_out<<<NB_N, 256>>>(emb_out_w, emb_out_b, (float*)d_out);
}

// round 4
// speedup vs baseline: 1.4155x; 1.0100x over previous
#include <cuda_runtime.h>

#define N_NODES 50000
#define N_EDGES 800000
#define HID 32
#define NLAYERS 4
#define SCAN_B 256
#define NBLK_SCAN ((N_NODES + SCAN_B - 1) / SCAN_B)   // 196

// ---------------- device scratch (no runtime allocation allowed) ----------------
__device__ float g_h[N_NODES * HID];      // node features
__device__ float g_x[N_NODES * 2];        // 2D coords (z provably stays 0)
__device__ float g_A[N_NODES * HID];      // h @ W1[0:32] + b1 (next layer's edge MLP)
__device__ float g_B[N_NODES * HID];      // h @ W1[32:64]
__device__ float g_agg[N_NODES * HID];    // edge-message sum per node
__device__ float g_xacc[N_NODES * 2];     // coord update accumulator
__device__ int   g_hist[N_NODES];         // per-row edge count
__device__ int   g_cur[N_NODES];          // scatter cursor (exclusive offsets)
__device__ int   g_btot[SCAN_B];          // per-block totals for hierarchical scan
__device__ int2  g_rc[N_EDGES];           // sorted (row, col)
__device__ float g_eas[N_EDGES];          // edge_attr permuted

__device__ __forceinline__ float silu(float x) {
    // x*sigmoid(x) = 0.5x*(1+tanh(0.5x)); tanh.approx err ~1e-4, fine at 1e-3 tol
    float h = 0.5f * x, t;
    asm("tanh.approx.f32 %0, %1;" : "=f"(t) : "f"(h));
    return fmaf(h, t, h);
}

__device__ __forceinline__ float2 ffma2(float2 a, float2 b, float2 c) {
    float2 d;
    asm("fma.rn.f32x2 %0, %1, %2, %3;"
        : "=l"(reinterpret_cast<unsigned long long&>(d))
        : "l"(reinterpret_cast<unsigned long long&>(a)),
          "l"(reinterpret_cast<unsigned long long&>(b)),
          "l"(reinterpret_cast<unsigned long long&>(c)));
    return d;
}

// out[32] = act(in[IN] @ Wsh + bias). Wsh [IN][32] row-major in shared, 16B aligned.
template<int IN, bool DOSILU, bool HASBIAS>
__device__ __forceinline__ void matvec32(const float* __restrict__ in,
                                         const float* __restrict__ Wsh,
                                         const float* __restrict__ bsh,
                                         float* __restrict__ out)
{
    float2 acc[16];
#pragma unroll
    for (int j = 0; j < 16; j++)
        acc[j] = HASBIAS ? reinterpret_cast<const float2*>(bsh)[j] : make_float2(0.f, 0.f);
#pragma unroll
    for (int i = 0; i < IN; i++) {
        float v = in[i];
        float2 vv = make_float2(v, v);
        const float4* w = reinterpret_cast<const float4*>(Wsh + i * 32);
#pragma unroll
        for (int j = 0; j < 8; j++) {
            float4 w4 = w[j];
            acc[2 * j]     = ffma2(vv, make_float2(w4.x, w4.y), acc[2 * j]);
            acc[2 * j + 1] = ffma2(vv, make_float2(w4.z, w4.w), acc[2 * j + 1]);
        }
    }
#pragma unroll
    for (int j = 0; j < 16; j++) {
        float a = acc[j].x, b = acc[j].y;
        if (DOSILU) { a = silu(a); b = silu(b); }
        out[2 * j] = a; out[2 * j + 1] = b;
    }
}

// store 32 floats as 8 float4
__device__ __forceinline__ void store32(float* dst, const float* v) {
#pragma unroll
    for (int j = 0; j < 8; j++)
        reinterpret_cast<float4*>(dst)[j] =
            make_float4(v[4 * j], v[4 * j + 1], v[4 * j + 2], v[4 * j + 3]);
}

// ---------------- init: h = [t,data]@emb_in + b; also A/B for layer 0 ----------------
__global__ __launch_bounds__(256) void k_init(
    const float* __restrict__ data, const float* __restrict__ pos,
    const float* __restrict__ tptr,
    const float* __restrict__ w, const float* __restrict__ b,
    const float* __restrict__ ew1, const float* __restrict__ eb1)
{
    __shared__ __align__(16) float sW[65 * 32];
    __shared__ __align__(16) float sE[64 * 32];
    __shared__ __align__(16) float sb[32], seb[32];
    int t = threadIdx.x;
    for (int i = t; i < 65 * 32; i += blockDim.x) sW[i] = w[i];
    for (int i = t; i < 64 * 32; i += blockDim.x) sE[i] = ew1[i];
    if (t < 32) { sb[t] = b[t]; seb[t] = eb1[t]; }
    __syncthreads();

    int n = blockIdx.x * blockDim.x + t;
    if (n >= N_NODES) return;

    float in[65];
    in[0] = tptr[0];
    const float4* dv = reinterpret_cast<const float4*>(data + n * 64);
#pragma unroll
    for (int i = 0; i < 16; i++) {
        float4 d = dv[i];
        in[1 + 4 * i + 0] = d.x; in[1 + 4 * i + 1] = d.y;
        in[1 + 4 * i + 2] = d.z; in[1 + 4 * i + 3] = d.w;
    }
    float hv[32];
    matvec32<65, false, true>(in, sW, sb, hv);
    store32(g_h + n * 32, hv);

    // A/B for layer 0 from this node's fresh h
    float a[32], bb[32];
    matvec32<32, false, true >(hv, sE,           seb, a);
    matvec32<32, false, false>(hv, sE + 32 * 32, seb, bb);
    store32(g_A + n * 32, a);
    store32(g_B + n * 32, bb);

    float4* aout = reinterpret_cast<float4*>(g_agg + n * 32);
#pragma unroll
    for (int j = 0; j < 8; j++) aout[j] = make_float4(0.f, 0.f, 0.f, 0.f);
    reinterpret_cast<float2*>(g_x)[n] = reinterpret_cast<const float2*>(pos)[n];
    reinterpret_cast<float2*>(g_xacc)[n] = make_float2(0.f, 0.f);
    g_hist[n] = 0;
}

// ---------------- counting sort of edges by row (hierarchical scan) ----------------
__global__ __launch_bounds__(256) void k_hist(const int* __restrict__ row)
{
    int e = blockIdx.x * blockDim.x + threadIdx.x;
    if (e < N_EDGES) atomicAdd(&g_hist[row[e]], 1);
}

__global__ __launch_bounds__(SCAN_B) void k_scan1()
{
    __shared__ int buf[SCAN_B];
    int t = threadIdx.x;
    int i = blockIdx.x * SCAN_B + t;
    int v = (i < N_NODES) ? g_hist[i] : 0;
    buf[t] = v;
    __syncthreads();
#pragma unroll
    for (int d = 1; d < SCAN_B; d <<= 1) {
        int x = (t >= d) ? buf[t - d] : 0;
        __syncthreads();
        buf[t] += x;
        __syncthreads();
    }
    if (i < N_NODES) g_cur[i] = buf[t] - v;            // block-local exclusive
    if (t == SCAN_B - 1) g_btot[blockIdx.x] = buf[t];  // block total
}

__global__ __launch_bounds__(SCAN_B) void k_scan2()
{
    __shared__ int buf[SCAN_B];
    int t = threadIdx.x;
    int v = (t < NBLK_SCAN) ? g_btot[t] : 0;
    buf[t] = v;
    __syncthreads();
#pragma unroll
    for (int d = 1; d < SCAN_B; d <<= 1) {
        int x = (t >= d) ? buf[t - d] : 0;
        __syncthreads();
        buf[t] += x;
        __syncthreads();
    }
    if (t < NBLK_SCAN) g_btot[t] = buf[t] - v;         // exclusive block offsets
}

__global__ __launch_bounds__(SCAN_B) void k_scan3()
{
    int i = blockIdx.x * SCAN_B + threadIdx.x;
    if (i < N_NODES) g_cur[i] += g_btot[blockIdx.x];
}

__global__ __launch_bounds__(256) void k_scatter(
    const int* __restrict__ row, const int* __restrict__ col,
    const float* __restrict__ ea)
{
    int e = blockIdx.x * blockDim.x + threadIdx.x;
    if (e >= N_EDGES) return;
    int r = row[e];
    int p = atomicAdd(&g_cur[r], 1);
    g_rc[p] = make_int2(r, col[e]);
    g_eas[p] = ea[e];
}

// ---------------- per layer: fused edge MLP + coord MLP, warp-per-32-edges ----------------
#define WPB 4   // warps per block; 800000 % (32*WPB) == 0 -> no bounds checks
__global__ __launch_bounds__(32 * WPB) void k_edge(
    const float* __restrict__ ew1,                       // layer slice of edge_w1 (66x32)
    const float* __restrict__ ew2, const float* __restrict__ eb2,
    const float* __restrict__ cw1, const float* __restrict__ cb1,
    const float* __restrict__ cw2)
{
    __shared__ __align__(16) float sW2[32 * 32];
    __shared__ __align__(16) float sC1[32 * 32];
    __shared__ __align__(16) float sb2[32], scb1[32], scw2[32], swr[32], swe[32];
    __shared__ __align__(16) float  sT[WPB][33 * 32];    // per-warp 32x32 tile (padded)
    __shared__ __align__(16) int2   sRC[WPB][32];        // (row, col) per edge
    __shared__ __align__(16) float2 sRE[WPB][32];        // (radial, edge_attr)

    int t = threadIdx.x;
    for (int i = t; i < 1024; i += blockDim.x) { sW2[i] = ew2[i]; sC1[i] = cw1[i]; }
    if (t < 32) {
        sb2[t] = eb2[t]; scb1[t] = cb1[t]; scw2[t] = cw2[t];
        swr[t] = ew1[64 * 32 + t]; swe[t] = ew1[65 * 32 + t];
    }
    __syncthreads();

    int warp = t >> 5, l = t & 31;
    int e = (blockIdx.x * WPB + warp) * 32 + l;
    float* T = sT[warp];

    int2 rc = g_rc[e];
    int r = rc.x, c = rc.y;
    float eav = g_eas[e];
    float2 xr = reinterpret_cast<const float2*>(g_x)[r];
    float2 xc = reinterpret_cast<const float2*>(g_x)[c];
    float dx = xr.x - xc.x, dy = xr.y - xc.y;
    float radial = dx * dx + dy * dy;
    float wrl = swr[l], wel = swe[l];

    sRC[warp][l] = rc;
    sRE[warp][l] = make_float2(radial, eav);
    __syncwarp();

    // cooperative t1 tile: iteration k = edge k of tile, lane l = feature l
#pragma unroll
    for (int k = 0; k < 32; k++) {
        int2   rck = sRC[warp][k];                       // broadcast LDS
        float2 rek = sRE[warp][k];
        float val = __ldg(&g_A[rck.x * 32 + l]) + __ldg(&g_B[rck.y * 32 + l])
                  + rek.x * wrl + rek.y * wel;
        T[l * 33 + k] = silu(val);                       // sT[feature][edge]
    }
    __syncwarp();

    // m = silu(t1 @ W2 + b2): lane l = edge l reads its t1 column
    float2 acc[16];
#pragma unroll
    for (int j = 0; j < 16; j++) acc[j] = reinterpret_cast<const float2*>(sb2)[j];
#pragma unroll
    for (int i = 0; i < 32; i++) {
        float v = T[i * 33 + l];
        float2 vv = make_float2(v, v);
        const float4* w = reinterpret_cast<const float4*>(sW2 + i * 32);
#pragma unroll
        for (int j = 0; j < 8; j++) {
            float4 w4 = w[j];
            acc[2 * j]     = ffma2(vv, make_float2(w4.x, w4.y), acc[2 * j]);
            acc[2 * j + 1] = ffma2(vv, make_float2(w4.z, w4.w), acc[2 * j + 1]);
        }
    }
    float m[32];
#pragma unroll
    for (int j = 0; j < 16; j++) { m[2 * j] = silu(acc[j].x); m[2 * j + 1] = silu(acc[j].y); }

    // coord MLP: phi = silu(m @ C1 + cb1) . cw2
#pragma unroll
    for (int j = 0; j < 16; j++) acc[j] = reinterpret_cast<const float2*>(scb1)[j];
#pragma unroll
    for (int i = 0; i < 32; i++) {
        float2 vv = make_float2(m[i], m[i]);
        const float4* w = reinterpret_cast<const float4*>(sC1 + i * 32);
#pragma unroll
        for (int j = 0; j < 8; j++) {
            float4 w4 = w[j];
            acc[2 * j]     = ffma2(vv, make_float2(w4.x, w4.y), acc[2 * j]);
            acc[2 * j + 1] = ffma2(vv, make_float2(w4.z, w4.w), acc[2 * j + 1]);
        }
    }
    float phi = 0.f;
#pragma unroll
    for (int j = 0; j < 16; j++) {
        phi = fmaf(silu(acc[j].x), scw2[2 * j],     phi);
        phi = fmaf(silu(acc[j].y), scw2[2 * j + 1], phi);
    }

    // store m tile: lane l writes its column (only lane l ever read column l)
#pragma unroll
    for (int j = 0; j < 32; j++) T[j * 33 + l] = m[j];

    // segment structure (rows sorted ascending within warp)
    int rprev = __shfl_up_sync(0xFFFFFFFFu, r, 1);
    bool head = (l == 0) || (r != rprev);
    unsigned mb = __ballot_sync(0xFFFFFFFFu, head);
    unsigned tailmask = (mb >> 1) | 0x80000000u;         // bit k: edge k is segment tail

    // coord segmented warp-reduction
    {
        float vx = dx * phi, vy = dy * phi;
        unsigned lem = 0xFFFFFFFFu >> (31 - l);
        int start = 31 - __clz(mb & lem);
#pragma unroll
        for (int d = 1; d < 32; d <<= 1) {
            float tx = __shfl_up_sync(0xFFFFFFFFu, vx, d);
            float ty = __shfl_up_sync(0xFFFFFFFFu, vy, d);
            if (l - d >= start) { vx += tx; vy += ty; }
        }
        if ((tailmask >> l) & 1u) {
            atomicAdd(&g_xacc[2 * r + 0], vx);
            atomicAdd(&g_xacc[2 * r + 1], vy);
        }
    }
    __syncwarp();

    // message aggregation: lane l = feature l sweeps sorted edges; tailmask is
    // warp-uniform -> segment-tail atomics are fully coalesced 128B REDs
    {
        float a = 0.f;
#pragma unroll
        for (int k = 0; k < 32; k++) {
            a += T[l * 33 + k];
            if ((tailmask >> k) & 1u) {
                atomicAdd(&g_agg[sRC[warp][k].x * 32 + l], a);
                a = 0.f;
            }
        }
    }
}

// ---------------- per layer: coord update + node MLP (residual) + next-layer A/B ----------------
template<bool NEXT>
__global__ __launch_bounds__(256) void k_node(
    const float* __restrict__ nw1, const float* __restrict__ nb1,
    const float* __restrict__ nw2, const float* __restrict__ nb2,
    const float* __restrict__ ew1n, const float* __restrict__ eb1n)
{
    __shared__ __align__(16) float sW1[64 * 32];
    __shared__ __align__(16) float sW2[32 * 32];
    __shared__ __align__(16) float sE[64 * 32];
    __shared__ __align__(16) float sb1[32], sb2[32], seb[32];
    int t = threadIdx.x;
    for (int i = t; i < 64 * 32; i += blockDim.x) sW1[i] = nw1[i];
    for (int i = t; i < 32 * 32; i += blockDim.x) sW2[i] = nw2[i];
    if (NEXT) for (int i = t; i < 64 * 32; i += blockDim.x) sE[i] = ew1n[i];
    if (t < 32) { sb1[t] = nb1[t]; sb2[t] = nb2[t]; if (NEXT) seb[t] = eb1n[t]; }
    __syncthreads();

    int n = blockIdx.x * blockDim.x + t;
    if (n >= N_NODES) return;

    float cnt = (float)max(g_hist[n], 1);
    float inv = __fdividef(1.0f, cnt);
    float2 xa = reinterpret_cast<float2*>(g_xacc)[n];
    float2 xv = reinterpret_cast<float2*>(g_x)[n];
    xv.x = fmaf(xa.x, inv, xv.x);
    xv.y = fmaf(xa.y, inv, xv.y);
    reinterpret_cast<float2*>(g_x)[n] = xv;
    reinterpret_cast<float2*>(g_xacc)[n] = make_float2(0.f, 0.f);

    float cat[64];
    float4* hio = reinterpret_cast<float4*>(g_h + n * 32);
    float4* agp = reinterpret_cast<float4*>(g_agg + n * 32);
#pragma unroll
    for (int i = 0; i < 8; i++) {
        float4 h4 = hio[i], a4 = agp[i];
        cat[4 * i + 0] = h4.x; cat[4 * i + 1] = h4.y; cat[4 * i + 2] = h4.z; cat[4 * i + 3] = h4.w;
        cat[32 + 4 * i + 0] = a4.x; cat[32 + 4 * i + 1] = a4.y;
        cat[32 + 4 * i + 2] = a4.z; cat[32 + 4 * i + 3] = a4.w;
        agp[i] = make_float4(0.f, 0.f, 0.f, 0.f);       // reset for next layer
    }
    float u[32];
    matvec32<64, true, true>(cat, sW1, sb1, u);
    float upd[32];
    matvec32<32, false, true>(u, sW2, sb2, upd);
    float hn[32];
#pragma unroll
    for (int i = 0; i < 32; i++) hn[i] = cat[i] + upd[i];
    store32(g_h + n * 32, hn);

    if (NEXT) {
        float a[32], bb[32];
        matvec32<32, false, true >(hn, sE,           seb, a);
        matvec32<32, false, false>(hn, sE + 32 * 32, seb, bb);
        store32(g_A + n * 32, a);
        store32(g_B + n * 32, bb);
    }
}

// ---------------- output projection ----------------
__global__ __launch_bounds__(256) void k_out(
    const float* __restrict__ w, const float* __restrict__ b,
    float* __restrict__ out)
{
    __shared__ __align__(16) float sW[32 * 64];
    __shared__ __align__(16) float sb[64];
    int t = threadIdx.x;
    for (int i = t; i < 32 * 64; i += blockDim.x) sW[i] = w[i];
    if (t < 64) sb[t] = b[t];
    __syncthreads();

    int n = blockIdx.x * blockDim.x + t;
    if (n >= N_NODES) return;

    float hv[32];
    const float4* hin = reinterpret_cast<const float4*>(g_h + n * 32);
#pragma unroll
    for (int i = 0; i < 8; i++) {
        float4 v = hin[i];
        hv[4 * i] = v.x; hv[4 * i + 1] = v.y; hv[4 * i + 2] = v.z; hv[4 * i + 3] = v.w;
    }
    float2 acc[32];
#pragma unroll
    for (int j = 0; j < 32; j++) acc[j] = reinterpret_cast<const float2*>(sb)[j];
#pragma unroll
    for (int i = 0; i < 32; i++) {
        float2 vv = make_float2(hv[i], hv[i]);
        const float4* wr = reinterpret_cast<const float4*>(sW + i * 64);
#pragma unroll
        for (int j = 0; j < 16; j++) {
            float4 w4 = wr[j];
            acc[2 * j]     = ffma2(vv, make_float2(w4.x, w4.y), acc[2 * j]);
            acc[2 * j + 1] = ffma2(vv, make_float2(w4.z, w4.w), acc[2 * j + 1]);
        }
    }
    float2* op = reinterpret_cast<float2*>(out + n * 64);
#pragma unroll
    for (int j = 0; j < 32; j++) op[j] = acc[j];
}

// ---------------- host launcher ----------------
extern "C" void kernel_launch(void* const* d_in, const int* in_sizes, int n_in,
                              void* d_out, int out_size)
{
    const float* data      = (const float*)d_in[0];
    const float* pos       = (const float*)d_in[1];
    const float* ea        = (const float*)d_in[2];
    const float* tptr      = (const float*)d_in[3];
    const int*   row       = (const int*)d_in[4];
    const int*   col       = (const int*)d_in[5];
    const float* emb_in_w  = (const float*)d_in[6];
    const float* emb_in_b  = (const float*)d_in[7];
    const float* emb_out_w = (const float*)d_in[8];
    const float* emb_out_b = (const float*)d_in[9];
    const float* edge_w1   = (const float*)d_in[10];
    const float* edge_b1   = (const float*)d_in[11];
    const float* edge_w2   = (const float*)d_in[12];
    const float* edge_b2   = (const float*)d_in[13];
    const float* node_w1   = (const float*)d_in[14];
    const float* node_b1   = (const float*)d_in[15];
    const float* node_w2   = (const float*)d_in[16];
    const float* node_b2   = (const float*)d_in[17];
    const float* coord_w1  = (const float*)d_in[18];
    const float* coord_b1  = (const float*)d_in[19];
    const float* coord_w2  = (const float*)d_in[20];

    const int NB_N = (N_NODES + 255) / 256;
    const int NB_E = (N_EDGES + 255) / 256;
    const int NB_T = N_EDGES / (32 * WPB);               // 6250, exact

    k_init<<<NB_N, 256>>>(data, pos, tptr, emb_in_w, emb_in_b, edge_w1, edge_b1);
    k_hist<<<NB_E, 256>>>(row);
    k_scan1<<<NBLK_SCAN, SCAN_B>>>();
    k_scan2<<<1, SCAN_B>>>();
    k_scan3<<<NBLK_SCAN, SCAN_B>>>();
    k_scatter<<<NB_E, 256>>>(row, col, ea);

    for (int l = 0; l < NLAYERS; l++) {
        k_edge<<<NB_T, 32 * WPB>>>(edge_w1 + l * 66 * 32,
                              edge_w2 + l * 1024, edge_b2 + l * 32,
                              coord_w1 + l * 1024, coord_b1 + l * 32,
                              coord_w2 + l * 32);
        if (l < NLAYERS - 1)
            k_node<true><<<NB_N, 256>>>(node_w1 + l * 2048, node_b1 + l * 32,
                                        node_w2 + l * 1024, node_b2 + l * 32,
                                        edge_w1 + (l + 1) * 66 * 32, edge_b1 + (l + 1) * 32);
        else
            k_node<false><<<NB_N, 256>>>(node_w1 + l * 2048, node_b1 + l * 32,
                                         node_w2 + l * 1024, node_b2 + l * 32,
                                         nullptr, nullptr);
    }
    k_out<<<NB_N, 256>>>(emb_out_w, emb_out_b, (float*)d_out);
}

// round 5
// speedup vs baseline: 1.4879x; 1.0512x over previous
#include <cuda_runtime.h>

#define N_NODES 50000
#define N_EDGES 800000
#define HID 32
#define NLAYERS 4
#define SCAN_B 256
#define NBLK_SCAN ((N_NODES + SCAN_B - 1) / SCAN_B)   // 196
#define NB_N ((N_NODES + 255) / 256)                  // 196
#define NB_E ((N_EDGES + 255) / 256)                  // 3125

// ---------------- device scratch (no runtime allocation allowed) ----------------
__device__ float g_h[N_NODES * HID];      // node features
__device__ float g_x[N_NODES * 2];        // 2D coords (z provably stays 0)
__device__ float g_A[N_NODES * HID];      // h @ W1[0:32] + b1 (current layer edge MLP)
__device__ float g_B[N_NODES * HID];      // h @ W1[32:64]
__device__ float g_agg[N_NODES * HID];    // edge-message sum per node
__device__ float g_xacc[N_NODES * 2];     // coord update accumulator
__device__ int   g_hist[N_NODES];         // per-row edge count (zeroed by k_out)
__device__ int   g_cur[N_NODES];          // scatter cursor (exclusive offsets)
__device__ volatile unsigned g_flag[NBLK_SCAN]; // lookback scan state (zeroed by k_out)
__device__ int2  g_rc[N_EDGES];           // sorted (row, col)
__device__ float g_eas[N_EDGES];          // edge_attr permuted

__device__ __forceinline__ float silu(float x) {
    float h = 0.5f * x, t;
    asm("tanh.approx.f32 %0, %1;" : "=f"(t) : "f"(h));
    return fmaf(h, t, h);
}

__device__ __forceinline__ float2 ffma2(float2 a, float2 b, float2 c) {
    float2 d;
    asm("fma.rn.f32x2 %0, %1, %2, %3;"
        : "=l"(reinterpret_cast<unsigned long long&>(d))
        : "l"(reinterpret_cast<unsigned long long&>(a)),
          "l"(reinterpret_cast<unsigned long long&>(b)),
          "l"(reinterpret_cast<unsigned long long&>(c)));
    return d;
}

template<int IN, bool DOSILU, bool HASBIAS>
__device__ __forceinline__ void matvec32(const float* __restrict__ in,
                                         const float* __restrict__ Wsh,
                                         const float* __restrict__ bsh,
                                         float* __restrict__ out)
{
    float2 acc[16];
#pragma unroll
    for (int j = 0; j < 16; j++)
        acc[j] = HASBIAS ? reinterpret_cast<const float2*>(bsh)[j] : make_float2(0.f, 0.f);
#pragma unroll
    for (int i = 0; i < IN; i++) {
        float v = in[i];
        float2 vv = make_float2(v, v);
        const float4* w = reinterpret_cast<const float4*>(Wsh + i * 32);
#pragma unroll
        for (int j = 0; j < 8; j++) {
            float4 w4 = w[j];
            acc[2 * j]     = ffma2(vv, make_float2(w4.x, w4.y), acc[2 * j]);
            acc[2 * j + 1] = ffma2(vv, make_float2(w4.z, w4.w), acc[2 * j + 1]);
        }
    }
#pragma unroll
    for (int j = 0; j < 16; j++) {
        float a = acc[j].x, b = acc[j].y;
        if (DOSILU) { a = silu(a); b = silu(b); }
        out[2 * j] = a; out[2 * j + 1] = b;
    }
}

__device__ __forceinline__ void store32(float* dst, const float* v) {
#pragma unroll
    for (int j = 0; j < 8; j++)
        reinterpret_cast<float4*>(dst)[j] =
            make_float4(v[4 * j], v[4 * j + 1], v[4 * j + 2], v[4 * j + 3]);
}

// ---------------- launch 0: node init (+ layer-0 A/B) fused with edge histogram ----------------
__global__ __launch_bounds__(256) void k_inithist(
    const float* __restrict__ data, const float* __restrict__ pos,
    const float* __restrict__ tptr,
    const float* __restrict__ w, const float* __restrict__ b,
    const float* __restrict__ ew1, const float* __restrict__ eb1,
    const int* __restrict__ row)
{
    if (blockIdx.x >= NB_N) {                            // histogram part (g_hist pre-zeroed)
        int e = (blockIdx.x - NB_N) * 256 + threadIdx.x;
        if (e < N_EDGES) atomicAdd(&g_hist[row[e]], 1);
        return;
    }
    __shared__ __align__(16) float sW[65 * 32];
    __shared__ __align__(16) float sE[64 * 32];
    __shared__ __align__(16) float sb[32], seb[32];
    int t = threadIdx.x;
    for (int i = t; i < 65 * 32; i += blockDim.x) sW[i] = w[i];
    for (int i = t; i < 64 * 32; i += blockDim.x) sE[i] = ew1[i];
    if (t < 32) { sb[t] = b[t]; seb[t] = eb1[t]; }
    __syncthreads();

    int n = blockIdx.x * blockDim.x + t;
    if (n >= N_NODES) return;

    float in[65];
    in[0] = tptr[0];
    const float4* dv = reinterpret_cast<const float4*>(data + n * 64);
#pragma unroll
    for (int i = 0; i < 16; i++) {
        float4 d = dv[i];
        in[1 + 4 * i + 0] = d.x; in[1 + 4 * i + 1] = d.y;
        in[1 + 4 * i + 2] = d.z; in[1 + 4 * i + 3] = d.w;
    }
    float hv[32];
    matvec32<65, false, true>(in, sW, sb, hv);
    store32(g_h + n * 32, hv);

    float a[32], bb[32];
    matvec32<32, false, true >(hv, sE,           seb, a);
    matvec32<32, false, false>(hv, sE + 32 * 32, seb, bb);
    store32(g_A + n * 32, a);
    store32(g_B + n * 32, bb);

    float4* aout = reinterpret_cast<float4*>(g_agg + n * 32);
#pragma unroll
    for (int j = 0; j < 8; j++) aout[j] = make_float4(0.f, 0.f, 0.f, 0.f);
    reinterpret_cast<float2*>(g_x)[n] = reinterpret_cast<const float2*>(pos)[n];
    reinterpret_cast<float2*>(g_xacc)[n] = make_float2(0.f, 0.f);
}

// ---------------- launch 1: single-pass exclusive scan (decoupled lookback) ----------------
__global__ __launch_bounds__(SCAN_B) void k_scan_lb()
{
    __shared__ int buf[SCAN_B];
    __shared__ int s_excl;
    int b = blockIdx.x, t = threadIdx.x;
    int i = b * SCAN_B + t;
    int v = (i < N_NODES) ? g_hist[i] : 0;
    buf[t] = v;
    __syncthreads();
#pragma unroll
    for (int d = 1; d < SCAN_B; d <<= 1) {
        int x = (t >= d) ? buf[t - d] : 0;
        __syncthreads();
        buf[t] += x;
        __syncthreads();
    }
    int incl = buf[t];
    int total = buf[SCAN_B - 1];
    if (t == 0) {
        if (b == 0) { g_flag[0] = (2u << 30) | (unsigned)total; s_excl = 0; }
        else        { g_flag[b] = (1u << 30) | (unsigned)total; }
    }
    if (b > 0 && t < 32) {
        int excl = 0;
        int look = b - 1;
        while (true) {
            int idx = look - t;
            unsigned f;
            if (idx >= 0) { do { f = g_flag[idx]; } while ((f >> 30) == 0u); }
            else f = (2u << 30);                         // virtual prefix 0
            unsigned pm = __ballot_sync(0xFFFFFFFFu, (f >> 30) == 2u);
            int firstp = __ffs(pm) - 1;
            int val = (int)(f & 0x3FFFFFFFu);
            int contrib = pm ? ((t <= firstp) ? val : 0) : val;
#pragma unroll
            for (int d = 16; d; d >>= 1) contrib += __shfl_xor_sync(0xFFFFFFFFu, contrib, d);
            excl += contrib;
            if (pm) break;
            look -= 32;
        }
        if (t == 0) {
            g_flag[b] = (2u << 30) | (unsigned)(excl + total);
            s_excl = excl;
        }
    }
    __syncthreads();
    if (i < N_NODES) g_cur[i] = s_excl + incl - v;       // global exclusive prefix
}

// ---------------- launch 2: scatter edges into row-sorted order ----------------
__global__ __launch_bounds__(256) void k_scatter(
    const int* __restrict__ row, const int* __restrict__ col,
    const float* __restrict__ ea)
{
    int e = blockIdx.x * blockDim.x + threadIdx.x;
    if (e >= N_EDGES) return;
    int r = row[e];
    int p = atomicAdd(&g_cur[r], 1);
    g_rc[p] = make_int2(r, col[e]);
    g_eas[p] = ea[e];
}

// ---------------- launch 3 (+per layer): edge MLP + coord MLP, weight-columns in registers ----------------
#define WPB 4
#define EDGE_BLOCKS 444          // 148 SM x 3 resident blocks; warps grid-stride over tiles
#define TSTRIDE 36               // 16B-aligned float4 rows, 4-way conflict only on stores
__global__ __launch_bounds__(128, 3) void k_edge(
    const float* __restrict__ ew1,
    const float* __restrict__ ew2, const float* __restrict__ eb2,
    const float* __restrict__ cw1, const float* __restrict__ cb1,
    const float* __restrict__ cw2)
{
    __shared__ __align__(16) float  sT[WPB][TSTRIDE * 32];  // [feature][edge] activation tile
    __shared__ __align__(16) float4 sRCE[WPB][32];          // (r, c, radial, ea) per edge

    int t = threadIdx.x, warp = t >> 5, l = t & 31;
    float* T = sT[warp];

    // lane l owns output-feature column l of both weight matrices, in registers
    float w2col[32], c1col[32];
#pragma unroll
    for (int i = 0; i < 32; i++) {
        w2col[i] = __ldg(&ew2[i * 32 + l]);
        c1col[i] = __ldg(&cw1[i * 32 + l]);
    }
    float b2l  = __ldg(&eb2[l]), cb1l = __ldg(&cb1[l]), cw2l = __ldg(&cw2[l]);
    float wrl  = __ldg(&ew1[64 * 32 + l]), wel = __ldg(&ew1[65 * 32 + l]);

    const int NT = N_EDGES / 32;                 // 25000 tiles
    const int NW = EDGE_BLOCKS * WPB;            // persistent warps
    for (int tile = blockIdx.x * WPB + warp; tile < NT; tile += NW) {
        int e = tile * 32 + l;
        int2 rc = g_rc[e];
        float eav = g_eas[e];
        float2 xr = reinterpret_cast<const float2*>(g_x)[rc.x];
        float2 xc = reinterpret_cast<const float2*>(g_x)[rc.y];
        float dx = xr.x - xc.x, dy = xr.y - xc.y;
        float radial = dx * dx + dy * dy;
        __syncwarp();                            // prior iter's T reads done
        sRCE[warp][l] = make_float4(__int_as_float(rc.x), __int_as_float(rc.y), radial, eav);
        __syncwarp();

        // t1[edge k][feature l] -> T[l*TSTRIDE + k], staged to float4 stores
        {
            float tv[4];
#pragma unroll
            for (int k = 0; k < 32; k++) {
                float4 q4 = sRCE[warp][k];       // broadcast
                int rk = __float_as_int(q4.x), ck = __float_as_int(q4.y);
                float val = __ldg(&g_A[rk * 32 + l]) + __ldg(&g_B[ck * 32 + l])
                          + q4.z * wrl + q4.w * wel;
                tv[k & 3] = silu(val);
                if ((k & 3) == 3)
                    *reinterpret_cast<float4*>(&T[l * TSTRIDE + (k & ~3)]) =
                        make_float4(tv[0], tv[1], tv[2], tv[3]);
            }
        }
        __syncwarp();

        // m[k][l] = silu(sum_i t1[k][i] * W2[i][l] + b2[l]) -- weights in regs, t1 broadcast
        float2 acc[16];
#pragma unroll
        for (int kp = 0; kp < 16; kp++) acc[kp] = make_float2(b2l, b2l);
#pragma unroll
        for (int i = 0; i < 32; i++) {
            float2 wd = make_float2(w2col[i], w2col[i]);
            const float4* Trow = reinterpret_cast<const float4*>(&T[i * TSTRIDE]);
#pragma unroll
            for (int kq = 0; kq < 8; kq++) {
                float4 f4 = Trow[kq];            // broadcast LDS.128
                acc[2 * kq]     = ffma2(make_float2(f4.x, f4.y), wd, acc[2 * kq]);
                acc[2 * kq + 1] = ffma2(make_float2(f4.z, f4.w), wd, acc[2 * kq + 1]);
            }
        }
        float2 m[16];
#pragma unroll
        for (int kp = 0; kp < 16; kp++) m[kp] = make_float2(silu(acc[kp].x), silu(acc[kp].y));
        __syncwarp();                            // all lanes done reading t1
#pragma unroll
        for (int kq = 0; kq < 8; kq++)
            *reinterpret_cast<float4*>(&T[l * TSTRIDE + 4 * kq]) =
                make_float4(m[2 * kq].x, m[2 * kq].y, m[2 * kq + 1].x, m[2 * kq + 1].y);
        __syncwarp();

        // p[k][l] = silu(sum_i m[k][i] * C1[i][l] + cb1[l]); q = p * cw2[l]
#pragma unroll
        for (int kp = 0; kp < 16; kp++) acc[kp] = make_float2(cb1l, cb1l);
#pragma unroll
        for (int i = 0; i < 32; i++) {
            float2 wd = make_float2(c1col[i], c1col[i]);
            const float4* Trow = reinterpret_cast<const float4*>(&T[i * TSTRIDE]);
#pragma unroll
            for (int kq = 0; kq < 8; kq++) {
                float4 f4 = Trow[kq];
                acc[2 * kq]     = ffma2(make_float2(f4.x, f4.y), wd, acc[2 * kq]);
                acc[2 * kq + 1] = ffma2(make_float2(f4.z, f4.w), wd, acc[2 * kq + 1]);
            }
        }
        __syncwarp();                            // all lanes done reading m
#pragma unroll
        for (int kq = 0; kq < 8; kq++)
            *reinterpret_cast<float4*>(&T[l * TSTRIDE + 4 * kq]) =
                make_float4(silu(acc[2 * kq].x)     * cw2l,
                            silu(acc[2 * kq].y)     * cw2l,
                            silu(acc[2 * kq + 1].x) * cw2l,
                            silu(acc[2 * kq + 1].y) * cw2l);
        __syncwarp();

        // phi for own edge l = sum over features i of q[l][i]
        float phi = 0.f;
#pragma unroll
        for (int i = 0; i < 32; i++) phi += T[i * TSTRIDE + l];

        // segment masks (rows sorted ascending within tile)
        int r = rc.x;
        int rprev = __shfl_up_sync(0xFFFFFFFFu, r, 1);
        bool head = (l == 0) || (r != rprev);
        unsigned mb = __ballot_sync(0xFFFFFFFFu, head);
        unsigned tailmask = (mb >> 1) | 0x80000000u;

        // coord: segmented inclusive scan, tail lanes emit atomics
        {
            float vx = dx * phi, vy = dy * phi;
            unsigned lem = 0xFFFFFFFFu >> (31 - l);
            int start = 31 - __clz(mb & lem);
#pragma unroll
            for (int d = 1; d < 32; d <<= 1) {
                float tx = __shfl_up_sync(0xFFFFFFFFu, vx, d);
                float ty = __shfl_up_sync(0xFFFFFFFFu, vy, d);
                if (l - d >= start) { vx += tx; vy += ty; }
            }
            if ((tailmask >> l) & 1u) {
                atomicAdd(&g_xacc[2 * r + 0], vx);
                atomicAdd(&g_xacc[2 * r + 1], vy);
            }
        }

        // message aggregation: in-register sweep over edges; warp-uniform tails
        // -> one coalesced 128B RED per segment
        {
            float a = 0.f;
#pragma unroll
            for (int kp = 0; kp < 16; kp++) {
                a += m[kp].x;
                if ((tailmask >> (2 * kp)) & 1u) {
                    int rowk = __float_as_int(sRCE[warp][2 * kp].x);
                    atomicAdd(&g_agg[rowk * 32 + l], a);
                    a = 0.f;
                }
                a += m[kp].y;
                if ((tailmask >> (2 * kp + 1)) & 1u) {
                    int rowk = __float_as_int(sRCE[warp][2 * kp + 1].x);
                    atomicAdd(&g_agg[rowk * 32 + l], a);
                    a = 0.f;
                }
            }
        }
    }
}

// ---------------- per layer: coord update + node MLP (residual) + next-layer A/B ----------------
template<bool NEXT>
__global__ __launch_bounds__(256) void k_node(
    const float* __restrict__ nw1, const float* __restrict__ nb1,
    const float* __restrict__ nw2, const float* __restrict__ nb2,
    const float* __restrict__ ew1n, const float* __restrict__ eb1n)
{
    __shared__ __align__(16) float sW1[64 * 32];
    __shared__ __align__(16) float sW2[32 * 32];
    __shared__ __align__(16) float sE[64 * 32];
    __shared__ __align__(16) float sb1[32], sb2[32], seb[32];
    int t = threadIdx.x;
    for (int i = t; i < 64 * 32; i += blockDim.x) sW1[i] = nw1[i];
    for (int i = t; i < 32 * 32; i += blockDim.x) sW2[i] = nw2[i];
    if (NEXT) for (int i = t; i < 64 * 32; i += blockDim.x) sE[i] = ew1n[i];
    if (t < 32) { sb1[t] = nb1[t]; sb2[t] = nb2[t]; if (NEXT) seb[t] = eb1n[t]; }
    __syncthreads();

    int n = blockIdx.x * blockDim.x + t;
    if (n >= N_NODES) return;

    float cnt = (float)max(g_hist[n], 1);
    float inv = __fdividef(1.0f, cnt);
    float2 xa = reinterpret_cast<float2*>(g_xacc)[n];
    float2 xv = reinterpret_cast<float2*>(g_x)[n];
    xv.x = fmaf(xa.x, inv, xv.x);
    xv.y = fmaf(xa.y, inv, xv.y);
    reinterpret_cast<float2*>(g_x)[n] = xv;
    reinterpret_cast<float2*>(g_xacc)[n] = make_float2(0.f, 0.f);

    float cat[64];
    float4* hio = reinterpret_cast<float4*>(g_h + n * 32);
    float4* agp = reinterpret_cast<float4*>(g_agg + n * 32);
#pragma unroll
    for (int i = 0; i < 8; i++) {
        float4 h4 = hio[i], a4 = agp[i];
        cat[4 * i + 0] = h4.x; cat[4 * i + 1] = h4.y; cat[4 * i + 2] = h4.z; cat[4 * i + 3] = h4.w;
        cat[32 + 4 * i + 0] = a4.x; cat[32 + 4 * i + 1] = a4.y;
        cat[32 + 4 * i + 2] = a4.z; cat[32 + 4 * i + 3] = a4.w;
        agp[i] = make_float4(0.f, 0.f, 0.f, 0.f);
    }
    float u[32];
    matvec32<64, true, true>(cat, sW1, sb1, u);
    float upd[32];
    matvec32<32, false, true>(u, sW2, sb2, upd);
    float hn[32];
#pragma unroll
    for (int i = 0; i < 32; i++) hn[i] = cat[i] + upd[i];
    store32(g_h + n * 32, hn);

    if (NEXT) {
        float a[32], bb[32];
        matvec32<32, false, true >(hn, sE,           seb, a);
        matvec32<32, false, false>(hn, sE + 32 * 32, seb, bb);
        store32(g_A + n * 32, a);
        store32(g_B + n * 32, bb);
    }
}

// ---------------- output projection + state reset for next graph replay ----------------
__global__ __launch_bounds__(256) void k_out(
    const float* __restrict__ w, const float* __restrict__ b,
    float* __restrict__ out)
{
    __shared__ __align__(16) float sW[32 * 64];
    __shared__ __align__(16) float sb[64];
    int t = threadIdx.x;
    for (int i = t; i < 32 * 64; i += blockDim.x) sW[i] = w[i];
    if (t < 64) sb[t] = b[t];
    __syncthreads();

    int n = blockIdx.x * blockDim.x + t;
    if (n >= N_NODES) return;

    g_hist[n] = 0;                                       // reset for next replay
    if (blockIdx.x == 0 && t < NBLK_SCAN) g_flag[t] = 0; // reset scan state

    float hv[32];
    const float4* hin = reinterpret_cast<const float4*>(g_h + n * 32);
#pragma unroll
    for (int i = 0; i < 8; i++) {
        float4 v = hin[i];
        hv[4 * i] = v.x; hv[4 * i + 1] = v.y; hv[4 * i + 2] = v.z; hv[4 * i + 3] = v.w;
    }
    float2 acc[32];
#pragma unroll
    for (int j = 0; j < 32; j++) acc[j] = reinterpret_cast<const float2*>(sb)[j];
#pragma unroll
    for (int i = 0; i < 32; i++) {
        float2 vv = make_float2(hv[i], hv[i]);
        const float4* wr = reinterpret_cast<const float4*>(sW + i * 64);
#pragma unroll
        for (int j = 0; j < 16; j++) {
            float4 w4 = wr[j];
            acc[2 * j]     = ffma2(vv, make_float2(w4.x, w4.y), acc[2 * j]);
            acc[2 * j + 1] = ffma2(vv, make_float2(w4.z, w4.w), acc[2 * j + 1]);
        }
    }
    float2* op = reinterpret_cast<float2*>(out + n * 64);
#pragma unroll
    for (int j = 0; j < 32; j++) op[j] = acc[j];
}

// ---------------- host launcher ----------------
extern "C" void kernel_launch(void* const* d_in, const int* in_sizes, int n_in,
                              void* d_out, int out_size)
{
    const float* data      = (const float*)d_in[0];
    const float* pos       = (const float*)d_in[1];
    const float* ea        = (const float*)d_in[2];
    const float* tptr      = (const float*)d_in[3];
    const int*   row       = (const int*)d_in[4];
    const int*   col       = (const int*)d_in[5];
    const float* emb_in_w  = (const float*)d_in[6];
    const float* emb_in_b  = (const float*)d_in[7];
    const float* emb_out_w = (const float*)d_in[8];
    const float* emb_out_b = (const float*)d_in[9];
    const float* edge_w1   = (const float*)d_in[10];
    const float* edge_b1   = (const float*)d_in[11];
    const float* edge_w2   = (const float*)d_in[12];
    const float* edge_b2   = (const float*)d_in[13];
    const float* node_w1   = (const float*)d_in[14];
    const float* node_b1   = (const float*)d_in[15];
    const float* node_w2   = (const float*)d_in[16];
    const float* node_b2   = (const float*)d_in[17];
    const float* coord_w1  = (const float*)d_in[18];
    const float* coord_b1  = (const float*)d_in[19];
    const float* coord_w2  = (const float*)d_in[20];

    k_inithist<<<NB_N + NB_E, 256>>>(data, pos, tptr, emb_in_w, emb_in_b,
                                     edge_w1, edge_b1, row);      // launch 0
    k_scan_lb<<<NBLK_SCAN, SCAN_B>>>();                           // launch 1
    k_scatter<<<NB_E, 256>>>(row, col, ea);                       // launch 2

    for (int l = 0; l < NLAYERS; l++) {
        k_edge<<<EDGE_BLOCKS, 32 * WPB>>>(edge_w1 + l * 66 * 32,  // launch 3 = first k_edge
                              edge_w2 + l * 1024, edge_b2 + l * 32,
                              coord_w1 + l * 1024, coord_b1 + l * 32,
                              coord_w2 + l * 32);
        if (l < NLAYERS - 1)
            k_node<true><<<NB_N, 256>>>(node_w1 + l * 2048, node_b1 + l * 32,
                                        node_w2 + l * 1024, node_b2 + l * 32,
                                        edge_w1 + (l + 1) * 66 * 32, edge_b1 + (l + 1) * 32);
        else
            k_node<false><<<NB_N, 256>>>(node_w1 + l * 2048, node_b1 + l * 32,
                                         node_w2 + l * 1024, node_b2 + l * 32,
                                         nullptr, nullptr);
    }
    k_out<<<NB_N, 256>>>(emb_out_w, emb_out_b, (float*)d_out);
}